// round 9
// baseline (speedup 1.0000x reference)
#include <cuda_runtime.h>
#include <cuda_fp16.h>

#define N_MAX 131072
#define E_MAX 2100000

// scratch (static __device__ arrays; zero-initialized at module load)
__device__ __half g_hh[N_MAX * 64]; // projected features (fp16 storage, fp32 math)
__device__ float g_as[N_MAX * 8];    // a_src per node/head
__device__ float g_ad[N_MAX * 8];    // a_dst per node/head
__device__ float g_wt[64 * 128];     // W transposed: [c][k]
__device__ int   g_deg[N_MAX];       // zeroed by consumer (aggregate) each call
__device__ int   g_row[N_MAX];       // CSR row start (by dst, unordered bases)
__device__ int   g_pos[E_MAX];       // per-edge rank within its dst
__device__ int   g_csr[E_MAX];       // src node per CSR slot
__device__ int   g_total;            // zeroed by consumer (aggregate) each call

// ---------------------------------------------------------------------------
// 1) in-degree histogram over dst; atomicAdd return = edge's rank (saved for
//    atomic-free scatter). Also transposes W (independent threads).
__global__ void degree_kernel(const int* __restrict__ ei,
                              const float* __restrict__ W, int E, int N) {
    int tid = blockIdx.x * blockDim.x + threadIdx.x;
    if (tid < 64 * 128) {
        int c = tid & 63;
        int k = tid >> 6;
        g_wt[c * 128 + k] = W[tid];
    }
    int q = (E + 3) >> 2;
    if (tid >= q) return;
    #pragma unroll
    for (int p = 0; p < 4; p++) {
        int e = tid + p * q;
        if (e < E) {
            int d = ei[E + e];
            if ((unsigned)d < (unsigned)N)
                g_pos[e] = atomicAdd(&g_deg[d], 1);
        }
    }
}

// 2) row-base assignment: warp-aggregated atomic offsets (bases unordered = fine)
__global__ void offsets_kernel(int N) {
    int i = blockIdx.x * blockDim.x + threadIdx.x;
    int lane = threadIdx.x & 31;
    int v = (i < N) ? g_deg[i] : 0;
    int xsum = v;
    #pragma unroll
    for (int o = 1; o < 32; o <<= 1) {
        int y = __shfl_up_sync(0xffffffffu, xsum, o);
        if (lane >= o) xsum += y;
    }
    int tot = __shfl_sync(0xffffffffu, xsum, 31);
    int base = 0;
    if (lane == 31) base = atomicAdd(&g_total, tot);
    base = __shfl_sync(0xffffffffu, base, 31);
    if (i < N) g_row[i] = base + xsum - v;
}

// 3) scatter edges into CSR slots — ATOMIC-FREE (slot = row[d] + pos[e])
__global__ void scatter_kernel(const int* __restrict__ ei, int E, int N) {
    int q = (E + 3) >> 2;
    int tid = blockIdx.x * blockDim.x + threadIdx.x;
    if (tid >= q) return;
    #pragma unroll
    for (int p = 0; p < 4; p++) {
        int e = tid + p * q;
        if (e < E) {
            int s = ei[e];
            int d = ei[E + e];
            if ((unsigned)d < (unsigned)N && (unsigned)s < (unsigned)N)
                g_csr[g_row[d] + g_pos[e]] = s;
        }
    }
}

// ---------------------------------------------------------------------------
// 4) GEMM h = x@W via fma.rn.f32x2, 8 nodes x 8 channels per thread,
//    128 threads/block, 128 nodes/block; + fused a_src/a_dst reduction.
#define XS_STRIDE 36   // 32 k + pad4
#define WS_STRIDE 36

#define FFMA2(d, a, b) asm("fma.rn.f32x2 %0, %1, %2, %0;" : "+l"(d) : "l"(a), "l"(b))

__global__ __launch_bounds__(128) void gemm_att_kernel(
        const float* __restrict__ x,
        const float* __restrict__ attS,
        const float* __restrict__ attD, int N) {
    __shared__ float ws[64 * WS_STRIDE];
    __shared__ float xs[128 * XS_STRIDE];
    int t = threadIdx.x;
    int cg = t & 7;        // channel group: c = cg + 8*i  (i == head!)
    int ng = t >> 3;       // node group:    n = node0 + ng + 16*j
    int node0 = blockIdx.x * 128;

    unsigned long long acc[8][8];
    #pragma unroll
    for (int j = 0; j < 8; j++)
        #pragma unroll
        for (int i = 0; i < 8; i++) acc[j][i] = 0ull;

    for (int kc = 0; kc < 4; kc++) {       // 4 chunks of 32 k
        __syncthreads();
        #pragma unroll
        for (int p = 0; p < 4; p++) {
            int idx = t + 128 * p;          // 0..511
            int c  = idx >> 3;
            int k4 = idx & 7;
            float4 v = ((const float4*)g_wt)[c * 32 + kc * 8 + k4];
            *(float4*)&ws[c * WS_STRIDE + k4 * 4] = v;
        }
        #pragma unroll
        for (int p = 0; p < 8; p++) {
            int idx = t + 128 * p;          // 0..1023
            int nn = idx >> 3;
            int k4 = idx & 7;
            int n = node0 + nn;
            float4 v = make_float4(0.f, 0.f, 0.f, 0.f);
            if (n < N) v = ((const float4*)x)[n * 32 + kc * 8 + k4];
            *(float4*)&xs[nn * XS_STRIDE + k4 * 4] = v;
        }
        __syncthreads();

        #pragma unroll
        for (int k4 = 0; k4 < 8; k4++) {
            ulonglong2 wv[8], xv[8];
            #pragma unroll
            for (int i = 0; i < 8; i++)
                wv[i] = *(const ulonglong2*)&ws[(cg + 8 * i) * WS_STRIDE + k4 * 4];
            #pragma unroll
            for (int j = 0; j < 8; j++)
                xv[j] = *(const ulonglong2*)&xs[(ng + 16 * j) * XS_STRIDE + k4 * 4];
            #pragma unroll
            for (int j = 0; j < 8; j++)
                #pragma unroll
                for (int i = 0; i < 8; i++) {
                    FFMA2(acc[j][i], xv[j].x, wv[i].x);
                    FFMA2(acc[j][i], xv[j].y, wv[i].y);
                }
        }
    }

    float aS[8], aD[8];
    #pragma unroll
    for (int i = 0; i < 8; i++) { aS[i] = attS[cg + 8 * i]; aD[i] = attD[cg + 8 * i]; }

    #pragma unroll
    for (int j = 0; j < 8; j++) {
        int n = node0 + ng + 16 * j;
        bool valid = (n < N);
        #pragma unroll
        for (int i = 0; i < 8; i++) {
            union { unsigned long long u; float2 f; } cv;
            cv.u = acc[j][i];
            float v = cv.f.x + cv.f.y;
            if (valid) g_hh[(long)n * 64 + cg + 8 * i] = __float2half_rn(v);
            float ps = v * aS[i];
            float pd = v * aD[i];
            ps += __shfl_down_sync(0xffffffffu, ps, 4, 8);
            ps += __shfl_down_sync(0xffffffffu, ps, 2, 8);
            ps += __shfl_down_sync(0xffffffffu, ps, 1, 8);
            pd += __shfl_down_sync(0xffffffffu, pd, 4, 8);
            pd += __shfl_down_sync(0xffffffffu, pd, 2, 8);
            pd += __shfl_down_sync(0xffffffffu, pd, 1, 8);
            if (cg == 0 && valid) {
                g_as[n * 8 + i] = ps;
                g_ad[n * 8 + i] = pd;
            }
        }
    }
}

// ---------------------------------------------------------------------------
// 5) warp-per-node softmax + gather; half-warp per edge, 4 channels/lane.
//    Full 32-edge batches run mask-free; tail batch masks.
//    Consumer-reset: zeroes g_deg[n] and g_total for the next call.
__global__ void aggregate_kernel(const float* __restrict__ bias,
                                 float* __restrict__ out, int N) {
    int warp = (blockIdx.x * blockDim.x + threadIdx.x) >> 5;
    int lane = threadIdx.x & 31;
    if (warp >= N) return;
    int n    = warp;
    int l16  = lane & 15;
    int half = lane >> 4;
    int c0   = l16 * 4;        // 4 channels per lane
    int hl   = l16 >> 1;       // head for this lane

    float adn = g_ad[n * 8 + hl];
    float asn = g_as[n * 8 + hl];
    int rs = g_row[n];
    int re = rs + g_deg[n];
    if (lane == 0) g_deg[n] = 0;                 // reset for next call
    if (warp == 0 && lane == 1) g_total = 0;     // reset for next call

    float a0 = 0.f, a1 = 0.f, a2 = 0.f, a3 = 0.f, ssum = 0.f;
    if (half == 0) {   // self loop on first half-warp
        float e0 = asn + adn;
        e0 = fmaxf(e0, 0.2f * e0);
        float ex = __expf(e0);
        uint2 u = *(const uint2*)&g_hh[(long)n * 64 + c0];
        float2 f01 = __half22float2(*(__half2*)&u.x);
        float2 f23 = __half22float2(*(__half2*)&u.y);
        ssum = ex;
        a0 = ex * f01.x; a1 = ex * f01.y;
        a2 = ex * f23.x; a3 = ex * f23.y;
    }

    int base = rs;
    for (; base + 32 <= re; base += 32) {        // full batches: no masking
        int sv = g_csr[base + lane];
        #pragma unroll 4
        for (int it = 0; it < 32; it += 2) {
            int s = __shfl_sync(0xffffffffu, sv, it + half);
            float as = g_as[s * 8 + hl];
            uint2 u = *(const uint2*)&g_hh[(long)s * 64 + c0];
            float e = as + adn;
            e = fmaxf(e, 0.2f * e);
            float xv = __expf(e);
            float2 f01 = __half22float2(*(__half2*)&u.x);
            float2 f23 = __half22float2(*(__half2*)&u.y);
            ssum += xv;
            a0 += xv * f01.x; a1 += xv * f01.y;
            a2 += xv * f23.x; a3 += xv * f23.y;
        }
    }
    if (base < re) {                              // tail batch: masked
        int cnt = re - base;
        int sv = (lane < cnt) ? g_csr[base + lane] : 0;
        for (int it = 0; it < cnt; it += 2) {
            int idx = it + half;
            int s = __shfl_sync(0xffffffffu, sv, idx);
            float as = g_as[s * 8 + hl];
            uint2 u = *(const uint2*)&g_hh[(long)s * 64 + c0];
            float e = as + adn;
            e = fmaxf(e, 0.2f * e);
            float xv = __expf(e);
            if (idx >= cnt) xv = 0.f;
            float2 f01 = __half22float2(*(__half2*)&u.x);
            float2 f23 = __half22float2(*(__half2*)&u.y);
            ssum += xv;
            a0 += xv * f01.x; a1 += xv * f01.y;
            a2 += xv * f23.x; a3 += xv * f23.y;
        }
    }

    // combine halves
    a0   += __shfl_down_sync(0xffffffffu, a0,   16);
    a1   += __shfl_down_sync(0xffffffffu, a1,   16);
    a2   += __shfl_down_sync(0xffffffffu, a2,   16);
    a3   += __shfl_down_sync(0xffffffffu, a3,   16);
    ssum += __shfl_down_sync(0xffffffffu, ssum, 16);

    if (half == 0) {
        float inv = 1.0f / ssum;
        float4 bv = ((const float4*)bias)[l16];
        float4 o;
        o.x = a0 * inv + bv.x;
        o.y = a1 * inv + bv.y;
        o.z = a2 * inv + bv.z;
        o.w = a3 * inv + bv.w;
        ((float4*)out)[(long)n * 16 + l16] = o;
    }
}

// ---------------------------------------------------------------------------
extern "C" void kernel_launch(void* const* d_in, const int* in_sizes, int n_in,
                              void* d_out, int out_size) {
    const float* x    = (const float*)d_in[0];
    const int*   ei   = (const int*)d_in[1];
    const float* W    = (const float*)d_in[2];
    const float* attS = (const float*)d_in[3];
    const float* attD = (const float*)d_in[4];
    const float* bias = (const float*)d_in[5];
    float*       out  = (float*)d_out;

    int N = in_sizes[0] / 128;
    int E = in_sizes[1] / 2;
    int Eq = (E + 3) / 4;
    int Dg = (Eq > 64 * 128) ? Eq : 64 * 128;

    degree_kernel   <<<(Dg + 255) / 256, 256>>>(ei, W, E, N);
    offsets_kernel  <<<(N + 255) / 256, 256>>>(N);
    scatter_kernel  <<<(Eq + 255) / 256, 256>>>(ei, E, N);
    gemm_att_kernel <<<(N + 127) / 128, 128>>>(x, attS, attD, N);
    aggregate_kernel<<<((long)N * 32 + 255) / 256, 256>>>(bias, out, N);
}

// round 10
// speedup vs baseline: 1.4080x; 1.4080x over previous
#include <cuda_runtime.h>
#include <cuda_fp16.h>

#define N_MAX 131072
#define E_MAX 2100000

// scratch (static __device__ arrays; no allocation)
__device__ __half g_hh[N_MAX * 64]; // projected features (fp16 storage, fp32 math)
__device__ float g_as[N_MAX * 8];    // a_src per node/head
__device__ float g_ad[N_MAX * 8];    // a_dst per node/head
__device__ float g_wt[64 * 128];     // W transposed: [c][k]
__device__ int   g_deg[N_MAX];
__device__ int   g_row[N_MAX];       // CSR row start (by dst, unordered bases)
__device__ int   g_cur[N_MAX];
__device__ int   g_csr[E_MAX];       // src node per CSR slot
__device__ int   g_total;

// ---------------------------------------------------------------------------
// 0) zero degree + global counter + transpose W (fused independent prep)
__global__ void prep_kernel(const float* __restrict__ W, int N) {
    int i = blockIdx.x * blockDim.x + threadIdx.x;
    if (i < N) g_deg[i] = 0;
    if (i < 64 * 128) {
        int c = i & 63;
        int k = i >> 6;
        g_wt[c * 128 + k] = W[i];
    }
    if (i == 0) g_total = 0;
}

// 1) in-degree histogram over dst; 4 independent coalesced edges per thread
//    (return value unused -> REDG fire-and-forget)
__global__ void degree_kernel(const int* __restrict__ ei, int E, int N) {
    int q = (E + 3) >> 2;
    int e = blockIdx.x * blockDim.x + threadIdx.x;
    if (e >= q) return;
    int d0 = -1, d1 = -1, d2 = -1, d3 = -1;
    d0 = ei[E + e];
    if (e + q     < E) d1 = ei[E + e + q];
    if (e + 2 * q < E) d2 = ei[E + e + 2 * q];
    if (e + 3 * q < E) d3 = ei[E + e + 3 * q];
    if ((unsigned)d0 < (unsigned)N) atomicAdd(&g_deg[d0], 1);
    if ((unsigned)d1 < (unsigned)N) atomicAdd(&g_deg[d1], 1);
    if ((unsigned)d2 < (unsigned)N) atomicAdd(&g_deg[d2], 1);
    if ((unsigned)d3 < (unsigned)N) atomicAdd(&g_deg[d3], 1);
}

// 2) row-base assignment: warp-aggregated atomic offsets (bases unordered = fine)
__global__ void offsets_kernel(int N) {
    int i = blockIdx.x * blockDim.x + threadIdx.x;
    int lane = threadIdx.x & 31;
    int v = (i < N) ? g_deg[i] : 0;
    int xsum = v;
    #pragma unroll
    for (int o = 1; o < 32; o <<= 1) {
        int y = __shfl_up_sync(0xffffffffu, xsum, o);
        if (lane >= o) xsum += y;
    }
    int tot = __shfl_sync(0xffffffffu, xsum, 31);
    int base = 0;
    if (lane == 31) base = atomicAdd(&g_total, tot);
    base = __shfl_sync(0xffffffffu, base, 31);
    if (i < N) {
        int st = base + xsum - v;
        g_row[i] = st;
        g_cur[i] = st;
    }
}

// 3) scatter edges into CSR slots; 4 independent coalesced edges per thread
__global__ void scatter_kernel(const int* __restrict__ ei, int E, int N) {
    int q = (E + 3) >> 2;
    int e = blockIdx.x * blockDim.x + threadIdx.x;
    if (e >= q) return;
    int s0 = 0, s1 = 0, s2 = 0, s3 = 0;
    int d0 = -1, d1 = -1, d2 = -1, d3 = -1;
    s0 = ei[e];           d0 = ei[E + e];
    if (e + q     < E) { s1 = ei[e + q];     d1 = ei[E + e + q]; }
    if (e + 2 * q < E) { s2 = ei[e + 2 * q]; d2 = ei[E + e + 2 * q]; }
    if (e + 3 * q < E) { s3 = ei[e + 3 * q]; d3 = ei[E + e + 3 * q]; }
    if ((unsigned)d0 < (unsigned)N && (unsigned)s0 < (unsigned)N)
        g_csr[atomicAdd(&g_cur[d0], 1)] = s0;
    if ((unsigned)d1 < (unsigned)N && (unsigned)s1 < (unsigned)N)
        g_csr[atomicAdd(&g_cur[d1], 1)] = s1;
    if ((unsigned)d2 < (unsigned)N && (unsigned)s2 < (unsigned)N)
        g_csr[atomicAdd(&g_cur[d2], 1)] = s2;
    if ((unsigned)d3 < (unsigned)N && (unsigned)s3 < (unsigned)N)
        g_csr[atomicAdd(&g_cur[d3], 1)] = s3;
}

// ---------------------------------------------------------------------------
// 4) GEMM h = x@W, warp-uniform W mapping:
//    warp w owns head w (channels 8w..8w+7, warp-uniform -> W loads broadcast);
//    thread covers 4 nodes (lane + 32j). acc = 8ch x 4n f32x2-over-k = 64 regs.
//    Epilogue: per-thread att reduction (no shuffles), 16B h store per node.
#define XS_STRIDE 36   // 32 k + pad4 (conflict-free v4 per 8-lane phase)

#define FFMA2(d, a, b) asm("fma.rn.f32x2 %0, %1, %2, %0;" : "+l"(d) : "l"(a), "l"(b))

__global__ __launch_bounds__(256, 2) void gemm_att_kernel(
        const float* __restrict__ x,
        const float* __restrict__ attS,
        const float* __restrict__ attD, int N) {
    __shared__ unsigned long long ws2[64 * 16];  // [c][k2] u64 pairs, 8 KB
    __shared__ float xs[128 * XS_STRIDE];        // 18 KB
    int t = threadIdx.x;
    int w = t >> 5;        // warp = head (0..7)
    int l = t & 31;        // lane = node row
    int node0 = blockIdx.x * 128;

    unsigned long long acc[8][4];   // [channel][node j]
    #pragma unroll
    for (int c = 0; c < 8; c++)
        #pragma unroll
        for (int j = 0; j < 4; j++) acc[c][j] = 0ull;

    for (int kc = 0; kc < 4; kc++) {       // 4 chunks of 32 k
        __syncthreads();
        // stage W chunk: 64c x 16 k2-pairs, u64 each; linear -> conflict-free
        #pragma unroll
        for (int p = 0; p < 4; p++) {
            int idx = t + 256 * p;          // 0..1023 = c*16 + k2
            int c  = idx >> 4;
            int k2 = idx & 15;
            ws2[idx] = ((const unsigned long long*)g_wt)[c * 64 + kc * 16 + k2];
        }
        // stage x chunk: 128n x 32k = 1024 float4, 4 per thread
        #pragma unroll
        for (int p = 0; p < 4; p++) {
            int idx = t + 256 * p;          // 0..1023
            int nn = idx >> 3;
            int k4 = idx & 7;
            int n = node0 + nn;
            float4 v = make_float4(0.f, 0.f, 0.f, 0.f);
            if (n < N) v = ((const float4*)x)[n * 32 + kc * 8 + k4];
            *(float4*)&xs[nn * XS_STRIDE + k4 * 4] = v;
        }
        __syncthreads();

        #pragma unroll
        for (int k4 = 0; k4 < 8; k4++) {
            // W: warp-uniform broadcast loads (16B each, 2 k2-pairs per channel)
            unsigned long long wva[8], wvb[8];
            #pragma unroll
            for (int c = 0; c < 8; c++) {
                ulonglong2 wq = *(const ulonglong2*)&ws2[(w * 8 + c) * 16 + k4 * 2];
                wva[c] = wq.x; wvb[c] = wq.y;
            }
            // x: 4 nodes, one 16B LDS each
            ulonglong2 xq[4];
            #pragma unroll
            for (int j = 0; j < 4; j++)
                xq[j] = *(const ulonglong2*)&xs[(l + 32 * j) * XS_STRIDE + k4 * 4];
            #pragma unroll
            for (int j = 0; j < 4; j++)
                #pragma unroll
                for (int c = 0; c < 8; c++) {
                    FFMA2(acc[c][j], xq[j].x, wva[c]);
                    FFMA2(acc[c][j], xq[j].y, wvb[c]);
                }
        }
    }

    // epilogue: per-thread head reduction, packed fp16 store
    float aS[8], aD[8];
    #pragma unroll
    for (int c = 0; c < 8; c++) { aS[c] = attS[w * 8 + c]; aD[c] = attD[w * 8 + c]; }

    #pragma unroll
    for (int j = 0; j < 4; j++) {
        int n = node0 + l + 32 * j;
        if (n >= N) continue;
        float v[8];
        float ps = 0.f, pd = 0.f;
        #pragma unroll
        for (int c = 0; c < 8; c++) {
            union { unsigned long long u; float2 f; } cv;
            cv.u = acc[c][j];
            v[c] = cv.f.x + cv.f.y;
            ps += v[c] * aS[c];
            pd += v[c] * aD[c];
        }
        union { uint4 u; __half2 h[4]; } pk;
        #pragma unroll
        for (int c = 0; c < 4; c++)
            pk.h[c] = __floats2half2_rn(v[2 * c], v[2 * c + 1]);
        *(uint4*)&g_hh[(long)n * 64 + w * 8] = pk.u;
        g_as[n * 8 + w] = ps;
        g_ad[n * 8 + w] = pd;
    }
}

// ---------------------------------------------------------------------------
// 5) warp-per-node softmax + gather; half-warp per edge, 4 channels/lane.
//    Full 32-edge batches run mask-free; tail batch masks.
__global__ void aggregate_kernel(const float* __restrict__ bias,
                                 float* __restrict__ out, int N) {
    int warp = (blockIdx.x * blockDim.x + threadIdx.x) >> 5;
    int lane = threadIdx.x & 31;
    if (warp >= N) return;
    int n    = warp;
    int l16  = lane & 15;
    int half = lane >> 4;
    int c0   = l16 * 4;        // 4 channels per lane
    int hl   = l16 >> 1;       // head for this lane

    float adn = g_ad[n * 8 + hl];
    float asn = g_as[n * 8 + hl];
    int rs = g_row[n];
    int re = rs + g_deg[n];

    float a0 = 0.f, a1 = 0.f, a2 = 0.f, a3 = 0.f, ssum = 0.f;
    if (half == 0) {   // self loop on first half-warp
        float e0 = asn + adn;
        e0 = fmaxf(e0, 0.2f * e0);
        float ex = __expf(e0);
        uint2 u = *(const uint2*)&g_hh[(long)n * 64 + c0];
        float2 f01 = __half22float2(*(__half2*)&u.x);
        float2 f23 = __half22float2(*(__half2*)&u.y);
        ssum = ex;
        a0 = ex * f01.x; a1 = ex * f01.y;
        a2 = ex * f23.x; a3 = ex * f23.y;
    }

    int base = rs;
    for (; base + 32 <= re; base += 32) {        // full batches: no masking
        int sv = g_csr[base + lane];
        #pragma unroll 4
        for (int it = 0; it < 32; it += 2) {
            int s = __shfl_sync(0xffffffffu, sv, it + half);
            float as = g_as[s * 8 + hl];
            uint2 u = *(const uint2*)&g_hh[(long)s * 64 + c0];
            float e = as + adn;
            e = fmaxf(e, 0.2f * e);
            float xv = __expf(e);
            float2 f01 = __half22float2(*(__half2*)&u.x);
            float2 f23 = __half22float2(*(__half2*)&u.y);
            ssum += xv;
            a0 += xv * f01.x; a1 += xv * f01.y;
            a2 += xv * f23.x; a3 += xv * f23.y;
        }
    }
    if (base < re) {                              // tail batch: masked
        int cnt = re - base;
        int sv = (lane < cnt) ? g_csr[base + lane] : 0;
        for (int it = 0; it < cnt; it += 2) {
            int idx = it + half;
            int s = __shfl_sync(0xffffffffu, sv, idx);
            float as = g_as[s * 8 + hl];
            uint2 u = *(const uint2*)&g_hh[(long)s * 64 + c0];
            float e = as + adn;
            e = fmaxf(e, 0.2f * e);
            float xv = __expf(e);
            if (idx >= cnt) xv = 0.f;
            float2 f01 = __half22float2(*(__half2*)&u.x);
            float2 f23 = __half22float2(*(__half2*)&u.y);
            ssum += xv;
            a0 += xv * f01.x; a1 += xv * f01.y;
            a2 += xv * f23.x; a3 += xv * f23.y;
        }
    }

    // combine halves
    a0   += __shfl_down_sync(0xffffffffu, a0,   16);
    a1   += __shfl_down_sync(0xffffffffu, a1,   16);
    a2   += __shfl_down_sync(0xffffffffu, a2,   16);
    a3   += __shfl_down_sync(0xffffffffu, a3,   16);
    ssum += __shfl_down_sync(0xffffffffu, ssum, 16);

    if (half == 0) {
        float inv = 1.0f / ssum;
        float4 bv = ((const float4*)bias)[l16];
        float4 o;
        o.x = a0 * inv + bv.x;
        o.y = a1 * inv + bv.y;
        o.z = a2 * inv + bv.z;
        o.w = a3 * inv + bv.w;
        ((float4*)out)[(long)n * 16 + l16] = o;
    }
}

// ---------------------------------------------------------------------------
extern "C" void kernel_launch(void* const* d_in, const int* in_sizes, int n_in,
                              void* d_out, int out_size) {
    const float* x    = (const float*)d_in[0];
    const int*   ei   = (const int*)d_in[1];
    const float* W    = (const float*)d_in[2];
    const float* attS = (const float*)d_in[3];
    const float* attD = (const float*)d_in[4];
    const float* bias = (const float*)d_in[5];
    float*       out  = (float*)d_out;

    int N = in_sizes[0] / 128;
    int E = in_sizes[1] / 2;
    int Eq = (E + 3) / 4;
    int P  = (N > 64 * 128) ? N : 64 * 128;

    prep_kernel     <<<(P + 255) / 256, 256>>>(W, N);
    degree_kernel   <<<(Eq + 255) / 256, 256>>>(ei, E, N);
    offsets_kernel  <<<(N + 255) / 256, 256>>>(N);
    scatter_kernel  <<<(Eq + 255) / 256, 256>>>(ei, E, N);
    gemm_att_kernel <<<(N + 127) / 128, 256>>>(x, attS, attD, N);
    aggregate_kernel<<<((long)N * 32 + 255) / 256, 256>>>(bias, out, N);
}

// round 12
// speedup vs baseline: 1.4644x; 1.0401x over previous
#include <cuda_runtime.h>
#include <cuda_fp16.h>

#define N_MAX 131072
#define E_MAX 2100000

// scratch (static __device__ arrays; no allocation)
__device__ __half g_hh[N_MAX * 64]; // projected features (fp16 storage, fp32 math)
__device__ float g_as[N_MAX * 8];    // a_src per node/head
__device__ float g_ad[N_MAX * 8];    // a_dst per node/head
__device__ float g_wt[64 * 128];     // W transposed: [c][k]
__device__ int   g_deg[N_MAX];
__device__ int   g_row[N_MAX];       // CSR row start (by dst, unordered bases)
__device__ int   g_cur[N_MAX];
__device__ int   g_csr[E_MAX];       // src node per CSR slot
__device__ int   g_total;

// ---------------------------------------------------------------------------
// 0) zero degree + global counter + transpose W (fused independent prep)
__global__ void prep_kernel(const float* __restrict__ W, int N) {
    int i = blockIdx.x * blockDim.x + threadIdx.x;
    if (i < N) g_deg[i] = 0;
    if (i < 64 * 128) {
        int c = i & 63;
        int k = i >> 6;
        g_wt[c * 128 + k] = W[i];
    }
    if (i == 0) g_total = 0;
}

// 1) in-degree histogram over dst; 4 independent coalesced edges per thread
//    (return value unused -> REDG fire-and-forget)
__global__ void degree_kernel(const int* __restrict__ ei, int E, int N) {
    int q = (E + 3) >> 2;
    int e = blockIdx.x * blockDim.x + threadIdx.x;
    if (e >= q) return;
    int d0 = -1, d1 = -1, d2 = -1, d3 = -1;
    d0 = ei[E + e];
    if (e + q     < E) d1 = ei[E + e + q];
    if (e + 2 * q < E) d2 = ei[E + e + 2 * q];
    if (e + 3 * q < E) d3 = ei[E + e + 3 * q];
    if ((unsigned)d0 < (unsigned)N) atomicAdd(&g_deg[d0], 1);
    if ((unsigned)d1 < (unsigned)N) atomicAdd(&g_deg[d1], 1);
    if ((unsigned)d2 < (unsigned)N) atomicAdd(&g_deg[d2], 1);
    if ((unsigned)d3 < (unsigned)N) atomicAdd(&g_deg[d3], 1);
}

// 2) row-base assignment: warp-aggregated atomic offsets (bases unordered = fine)
__global__ void offsets_kernel(int N) {
    int i = blockIdx.x * blockDim.x + threadIdx.x;
    int lane = threadIdx.x & 31;
    int v = (i < N) ? g_deg[i] : 0;
    int xsum = v;
    #pragma unroll
    for (int o = 1; o < 32; o <<= 1) {
        int y = __shfl_up_sync(0xffffffffu, xsum, o);
        if (lane >= o) xsum += y;
    }
    int tot = __shfl_sync(0xffffffffu, xsum, 31);
    int base = 0;
    if (lane == 31) base = atomicAdd(&g_total, tot);
    base = __shfl_sync(0xffffffffu, base, 31);
    if (i < N) {
        int st = base + xsum - v;
        g_row[i] = st;
        g_cur[i] = st;
    }
}

// 3) scatter edges into CSR slots; 4 independent coalesced edges per thread
__global__ void scatter_kernel(const int* __restrict__ ei, int E, int N) {
    int q = (E + 3) >> 2;
    int e = blockIdx.x * blockDim.x + threadIdx.x;
    if (e >= q) return;
    int s0 = 0, s1 = 0, s2 = 0, s3 = 0;
    int d0 = -1, d1 = -1, d2 = -1, d3 = -1;
    s0 = ei[e];           d0 = ei[E + e];
    if (e + q     < E) { s1 = ei[e + q];     d1 = ei[E + e + q]; }
    if (e + 2 * q < E) { s2 = ei[e + 2 * q]; d2 = ei[E + e + 2 * q]; }
    if (e + 3 * q < E) { s3 = ei[e + 3 * q]; d3 = ei[E + e + 3 * q]; }
    if ((unsigned)d0 < (unsigned)N && (unsigned)s0 < (unsigned)N)
        g_csr[atomicAdd(&g_cur[d0], 1)] = s0;
    if ((unsigned)d1 < (unsigned)N && (unsigned)s1 < (unsigned)N)
        g_csr[atomicAdd(&g_cur[d1], 1)] = s1;
    if ((unsigned)d2 < (unsigned)N && (unsigned)s2 < (unsigned)N)
        g_csr[atomicAdd(&g_cur[d2], 1)] = s2;
    if ((unsigned)d3 < (unsigned)N && (unsigned)s3 < (unsigned)N)
        g_csr[atomicAdd(&g_cur[d3], 1)] = s3;
}

// ---------------------------------------------------------------------------
// 4) GEMM h = x@W, warp-uniform W mapping, reduced live-register inner loop:
//    warp w = head w (W smem loads are warp-uniform broadcasts);
//    thread covers 4 nodes (lane + 32j), 8 channels; k2-granularity (u64 = 2 k).
//    Live set: acc 64 + wv 16 + xv 8 + addr ~15  -> fits 128-reg cap, occ 2.
#define FFMA2(d, a, b) asm("fma.rn.f32x2 %0, %1, %2, %0;" : "+l"(d) : "l"(a), "l"(b))

#define XS2_STRIDE 17   // u64 stride per node: 16 k2 + 1 pad

__global__ __launch_bounds__(256, 2) void gemm_att_kernel(
        const float* __restrict__ x,
        const float* __restrict__ attS,
        const float* __restrict__ attD, int N) {
    __shared__ unsigned long long ws2[64 * 16];           // [c][k2], 8 KB
    __shared__ unsigned long long xs2[128 * XS2_STRIDE];  // [n][k2], 17.4 KB
    int t = threadIdx.x;
    int w = t >> 5;        // warp = head (0..7)
    int l = t & 31;        // lane = node row
    int node0 = blockIdx.x * 128;

    unsigned long long acc[8][4];   // [channel][node j] f32x2-over-k
    #pragma unroll
    for (int c = 0; c < 8; c++)
        #pragma unroll
        for (int j = 0; j < 4; j++) acc[c][j] = 0ull;

    for (int kc = 0; kc < 4; kc++) {       // 4 chunks of 32 k
        __syncthreads();
        // stage W chunk: 64c x 16 k2, u64 each (coalesced from g_wt)
        #pragma unroll
        for (int p = 0; p < 4; p++) {
            int idx = t + 256 * p;          // 0..1023 = c*16 + k2
            int c  = idx >> 4;
            int k2 = idx & 15;
            ws2[idx] = ((const unsigned long long*)g_wt)[c * 64 + kc * 16 + k2];
        }
        // stage x chunk: 128n x 8 float4 -> u64 pairs at stride-17
        #pragma unroll
        for (int p = 0; p < 4; p++) {
            int idx = t + 256 * p;          // 0..1023
            int nn = idx >> 3;
            int k4 = idx & 7;
            int n = node0 + nn;
            float4 v = make_float4(0.f, 0.f, 0.f, 0.f);
            if (n < N) v = ((const float4*)x)[n * 32 + kc * 8 + k4];
            union { float4 f; unsigned long long u[2]; } cv;
            cv.f = v;
            xs2[nn * XS2_STRIDE + k4 * 2    ] = cv.u[0];
            xs2[nn * XS2_STRIDE + k4 * 2 + 1] = cv.u[1];
        }
        __syncthreads();

        #pragma unroll 4
        for (int k2 = 0; k2 < 16; k2++) {
            unsigned long long wv[8];       // warp-uniform broadcasts
            #pragma unroll
            for (int c = 0; c < 8; c++)
                wv[c] = ws2[(w * 8 + c) * 16 + k2];
            unsigned long long xv[4];
            #pragma unroll
            for (int j = 0; j < 4; j++)
                xv[j] = xs2[(l + 32 * j) * XS2_STRIDE + k2];
            #pragma unroll
            for (int j = 0; j < 4; j++)
                #pragma unroll
                for (int c = 0; c < 8; c++)
                    FFMA2(acc[c][j], xv[j], wv[c]);
        }
    }

    // epilogue: per-thread head reduction (no shuffles), packed fp16 store
    float aS[8], aD[8];
    #pragma unroll
    for (int c = 0; c < 8; c++) { aS[c] = attS[w * 8 + c]; aD[c] = attD[w * 8 + c]; }

    #pragma unroll
    for (int j = 0; j < 4; j++) {
        int n = node0 + l + 32 * j;
        if (n >= N) continue;
        float v[8];
        float ps = 0.f, pd = 0.f;
        #pragma unroll
        for (int c = 0; c < 8; c++) {
            union { unsigned long long u; float2 f; } cv;
            cv.u = acc[c][j];
            v[c] = cv.f.x + cv.f.y;
            ps += v[c] * aS[c];
            pd += v[c] * aD[c];
        }
        union { uint4 u; __half2 h[4]; } pk;
        #pragma unroll
        for (int c = 0; c < 4; c++)
            pk.h[c] = __floats2half2_rn(v[2 * c], v[2 * c + 1]);
        *(uint4*)&g_hh[(long)n * 64 + w * 8] = pk.u;
        g_as[n * 8 + w] = ps;
        g_ad[n * 8 + w] = pd;
    }
}

// ---------------------------------------------------------------------------
// 5) warp-per-node softmax + gather; half-warp per edge, 4 channels/lane.
//    Full 32-edge batches run mask-free; tail batch masks.
__global__ void aggregate_kernel(const float* __restrict__ bias,
                                 float* __restrict__ out, int N) {
    int warp = (blockIdx.x * blockDim.x + threadIdx.x) >> 5;
    int lane = threadIdx.x & 31;
    if (warp >= N) return;
    int n    = warp;
    int l16  = lane & 15;
    int half = lane >> 4;
    int c0   = l16 * 4;        // 4 channels per lane
    int hl   = l16 >> 1;       // head for this lane

    float adn = g_ad[n * 8 + hl];
    float asn = g_as[n * 8 + hl];
    int rs = g_row[n];
    int re = rs + g_deg[n];

    float a0 = 0.f, a1 = 0.f, a2 = 0.f, a3 = 0.f, ssum = 0.f;
    if (half == 0) {   // self loop on first half-warp
        float e0 = asn + adn;
        e0 = fmaxf(e0, 0.2f * e0);
        float ex = __expf(e0);
        uint2 u = *(const uint2*)&g_hh[(long)n * 64 + c0];
        float2 f01 = __half22float2(*(__half2*)&u.x);
        float2 f23 = __half22float2(*(__half2*)&u.y);
        ssum = ex;
        a0 = ex * f01.x; a1 = ex * f01.y;
        a2 = ex * f23.x; a3 = ex * f23.y;
    }

    int base = rs;
    for (; base + 32 <= re; base += 32) {        // full batches: no masking
        int sv = g_csr[base + lane];
        #pragma unroll 4
        for (int it = 0; it < 32; it += 2) {
            int s = __shfl_sync(0xffffffffu, sv, it + half);
            float as = g_as[s * 8 + hl];
            uint2 u = *(const uint2*)&g_hh[(long)s * 64 + c0];
            float e = as + adn;
            e = fmaxf(e, 0.2f * e);
            float xv = __expf(e);
            float2 f01 = __half22float2(*(__half2*)&u.x);
            float2 f23 = __half22float2(*(__half2*)&u.y);
            ssum += xv;
            a0 += xv * f01.x; a1 += xv * f01.y;
            a2 += xv * f23.x; a3 += xv * f23.y;
        }
    }
    if (base < re) {                              // tail batch: masked
        int cnt = re - base;
        int sv = (lane < cnt) ? g_csr[base + lane] : 0;
        for (int it = 0; it < cnt; it += 2) {
            int idx = it + half;
            int s = __shfl_sync(0xffffffffu, sv, idx);
            float as = g_as[s * 8 + hl];
            uint2 u = *(const uint2*)&g_hh[(long)s * 64 + c0];
            float e = as + adn;
            e = fmaxf(e, 0.2f * e);
            float xv = __expf(e);
            if (idx >= cnt) xv = 0.f;
            float2 f01 = __half22float2(*(__half2*)&u.x);
            float2 f23 = __half22float2(*(__half2*)&u.y);
            ssum += xv;
            a0 += xv * f01.x; a1 += xv * f01.y;
            a2 += xv * f23.x; a3 += xv * f23.y;
        }
    }

    // combine halves
    a0   += __shfl_down_sync(0xffffffffu, a0,   16);
    a1   += __shfl_down_sync(0xffffffffu, a1,   16);
    a2   += __shfl_down_sync(0xffffffffu, a2,   16);
    a3   += __shfl_down_sync(0xffffffffu, a3,   16);
    ssum += __shfl_down_sync(0xffffffffu, ssum, 16);

    if (half == 0) {
        float inv = 1.0f / ssum;
        float4 bv = ((const float4*)bias)[l16];
        float4 o;
        o.x = a0 * inv + bv.x;
        o.y = a1 * inv + bv.y;
        o.z = a2 * inv + bv.z;
        o.w = a3 * inv + bv.w;
        ((float4*)out)[(long)n * 16 + l16] = o;
    }
}

// ---------------------------------------------------------------------------
extern "C" void kernel_launch(void* const* d_in, const int* in_sizes, int n_in,
                              void* d_out, int out_size) {
    const float* x    = (const float*)d_in[0];
    const int*   ei   = (const int*)d_in[1];
    const float* W    = (const float*)d_in[2];
    const float* attS = (const float*)d_in[3];
    const float* attD = (const float*)d_in[4];
    const float* bias = (const float*)d_in[5];
    float*       out  = (float*)d_out;

    int N = in_sizes[0] / 128;
    int E = in_sizes[1] / 2;
    int Eq = (E + 3) / 4;
    int P  = (N > 64 * 128) ? N : 64 * 128;

    prep_kernel     <<<(P + 255) / 256, 256>>>(W, N);
    degree_kernel   <<<(Eq + 255) / 256, 256>>>(ei, E, N);
    offsets_kernel  <<<(N + 255) / 256, 256>>>(N);
    scatter_kernel  <<<(Eq + 255) / 256, 256>>>(ei, E, N);
    gemm_att_kernel <<<(N + 127) / 128, 256>>>(x, attS, attD, N);
    aggregate_kernel<<<((long)N * 32 + 255) / 256, 256>>>(bias, out, N);
}